// round 15
// baseline (speedup 1.0000x reference)
#include <cuda_runtime.h>
#include <cuda_fp16.h>
#include <cstdint>

#define N_NODES   100000
#define F_IN      65
#define F_HID     64
#define F_OUT     64
#define MAX_EDGES 1600000
#define NCHUNKS   ((N_NODES + 255) / 256)   // 391

// ---- scratch (~32.5MB; proven envelope) ------------------------------------
__device__ __align__(16) __half g_yh[(size_t)N_NODES * F_HID]; // y = x@W1 (fp16)
__device__ __align__(16) __half g_ah[(size_t)N_NODES * F_HID]; // relu(y+b1+agg) (fp16)
__device__ int g_srcs[MAX_EDGES];    // CSR: src indices grouped by dst
__device__ int g_cnt[N_NODES];       // counts -> excl prefix -> incl end
__device__ int g_bsum[NCHUNKS];      // per-chunk sums for scan
// STICKY flag: 0 = int64 (default), 1 = buffer holds int32 pairs.
__device__ int g_idx_is32;

// ---------------------------------------------------------------------------
// Kernel 1 (fused): zero counts + sampled dtype probe (set-only flag).
// ---------------------------------------------------------------------------
__global__ void init_kernel(const long long* __restrict__ ei, int nprobe) {
    int i = blockIdx.x * blockDim.x + threadIdx.x;
    if (i < N_NODES) g_cnt[i] = 0;
    bool bad = false;
    if (i < nprobe) {
        long long v = ei[i];
        bad = (v < 0) | (v >= N_NODES);
    }
    if (__syncthreads_or(bad) && threadIdx.x == 0) g_idx_is32 = 1;
}

// ---------------------------------------------------------------------------
// Kernel 2: GEMM1  y = x @ W1  (R5-proven scalar 64x64/4x4; stores fp16).
// ---------------------------------------------------------------------------
__global__ void gemm1_kernel(const float* __restrict__ x,
                             const float* __restrict__ W1,
                             int n) {
    __shared__ float shA[64 * 68];                     // [r][k], stride 68
    __shared__ __align__(16) float shW[F_IN * F_HID];  // [k][j]

    int tid  = threadIdx.x;
    int row0 = blockIdx.x * 64;

    for (int t = tid; t < 64 * F_IN; t += 256) {
        int r = t / F_IN;
        int c = t - r * F_IN;
        int row = row0 + r;
        shA[r * 68 + c] = (row < n) ? x[(size_t)row * F_IN + c] : 0.f;
    }
    for (int t = tid; t < F_IN * F_HID; t += 256) shW[t] = W1[t];
    __syncthreads();

    int ty = tid >> 4;
    int tx = tid & 15;

    float acc[4][4];
    #pragma unroll
    for (int i = 0; i < 4; i++)
        #pragma unroll
        for (int j = 0; j < 4; j++) acc[i][j] = 0.f;

    const float* ar = &shA[(ty * 4) * 68];
    #pragma unroll 5
    for (int k = 0; k < F_IN; k++) {
        float a0 = ar[0 * 68 + k];
        float a1 = ar[1 * 68 + k];
        float a2 = ar[2 * 68 + k];
        float a3 = ar[3 * 68 + k];
        float4 b = *reinterpret_cast<const float4*>(&shW[k * F_HID + tx * 4]);
        acc[0][0] = fmaf(a0, b.x, acc[0][0]); acc[0][1] = fmaf(a0, b.y, acc[0][1]);
        acc[0][2] = fmaf(a0, b.z, acc[0][2]); acc[0][3] = fmaf(a0, b.w, acc[0][3]);
        acc[1][0] = fmaf(a1, b.x, acc[1][0]); acc[1][1] = fmaf(a1, b.y, acc[1][1]);
        acc[1][2] = fmaf(a1, b.z, acc[1][2]); acc[1][3] = fmaf(a1, b.w, acc[1][3]);
        acc[2][0] = fmaf(a2, b.x, acc[2][0]); acc[2][1] = fmaf(a2, b.y, acc[2][1]);
        acc[2][2] = fmaf(a2, b.z, acc[2][2]); acc[2][3] = fmaf(a2, b.w, acc[2][3]);
        acc[3][0] = fmaf(a3, b.x, acc[3][0]); acc[3][1] = fmaf(a3, b.y, acc[3][1]);
        acc[3][2] = fmaf(a3, b.z, acc[3][2]); acc[3][3] = fmaf(a3, b.w, acc[3][3]);
    }

    #pragma unroll
    for (int i = 0; i < 4; i++) {
        int row = row0 + ty * 4 + i;
        if (row < n) {
            __half2 h0 = __floats2half2_rn(acc[i][0], acc[i][1]);
            __half2 h1 = __floats2half2_rn(acc[i][2], acc[i][3]);
            uint2 o = make_uint2(*reinterpret_cast<uint32_t*>(&h0),
                                 *reinterpret_cast<uint32_t*>(&h1));
            *reinterpret_cast<uint2*>(&g_yh[(size_t)row * F_HID + tx * 4]) = o;
        }
    }
}

// ---------------------------------------------------------------------------
// Kernel 3: histogram of dst (R7-proven 1-edge/thread).
// ---------------------------------------------------------------------------
__global__ void hist_kernel(const void* __restrict__ edge_index, int n_edges) {
    int e = blockIdx.x * blockDim.x + threadIdx.x;
    if (e >= n_edges) return;
    int dst;
    if (!g_idx_is32) dst = (int)((const long long*)edge_index)[(size_t)n_edges + e];
    else             dst = ((const int*)edge_index)[n_edges + e];
    atomicAdd(&g_cnt[dst], 1);
}

// ---------------------------------------------------------------------------
// Kernel 4a: per-chunk sums.
// ---------------------------------------------------------------------------
__global__ void chunk_sums_kernel() {
    __shared__ int s[256];
    int b = blockIdx.x, t = threadIdx.x;
    int i = b * 256 + t;
    s[t] = (i < N_NODES) ? g_cnt[i] : 0;
    __syncthreads();
    #pragma unroll
    for (int off = 128; off > 0; off >>= 1) {
        if (t < off) s[t] += s[t + off];
        __syncthreads();
    }
    if (t == 0) g_bsum[b] = s[0];
}

// ---------------------------------------------------------------------------
// Kernel 4b: combined scan. Block b reduces g_bsum[0..b) itself (<=391 adds
// over 256 threads), then exclusive-scans its own chunk with that base.
// ---------------------------------------------------------------------------
__global__ void scan_chunks2_kernel() {
    __shared__ int s[256];
    __shared__ int sbase;
    int b = blockIdx.x, t = threadIdx.x;

    int part = 0;
    for (int i = t; i < b; i += 256) part += g_bsum[i];
    s[t] = part;
    __syncthreads();
    #pragma unroll
    for (int off = 128; off > 0; off >>= 1) {
        if (t < off) s[t] += s[t + off];
        __syncthreads();
    }
    if (t == 0) sbase = s[0];
    __syncthreads();
    int base = sbase;
    __syncthreads();

    int i = b * 256 + t;
    int v = (i < N_NODES) ? g_cnt[i] : 0;
    s[t] = v;
    __syncthreads();
    #pragma unroll
    for (int off = 1; off < 256; off <<= 1) {
        int add = (t >= off) ? s[t - off] : 0;
        __syncthreads();
        s[t] += add;
        __syncthreads();
    }
    if (i < N_NODES) g_cnt[i] = base + s[t] - v;   // exclusive prefix
}

// ---------------------------------------------------------------------------
// Kernel 5: fill CSR (R7-proven 1-edge/thread).
// After this, g_cnt[d] = inclusive end offset of node d.
// ---------------------------------------------------------------------------
__global__ void fill_kernel(const void* __restrict__ edge_index, int n_edges) {
    int e = blockIdx.x * blockDim.x + threadIdx.x;
    if (e >= n_edges) return;
    int src, dst;
    if (!g_idx_is32) {
        const long long* p = (const long long*)edge_index;
        src = (int)p[e];
        dst = (int)p[(size_t)n_edges + e];
    } else {
        const int* p = (const int*)edge_index;
        src = p[e];
        dst = p[n_edges + e];
    }
    int pos = atomicAdd(&g_cnt[dst], 1);
    g_srcs[pos] = src;
}

// ---------------------------------------------------------------------------
// Kernel 6: aggregation + layer-1 epilogue (fp16 gathers, fp32 accumulate):
//   A[node] = relu( y[node] + b1 + sum_{src in-edges} y[src] )  -> fp16 g_ah
// 16-lane group per node; lane q owns halves [q*4, q*4+4); 8-way unroll.
// ---------------------------------------------------------------------------
__device__ __forceinline__ void acc_h4(float4& v, uint2 u) {
    __half2 h0 = *reinterpret_cast<__half2*>(&u.x);
    __half2 h1 = *reinterpret_cast<__half2*>(&u.y);
    float2 f0 = __half22float2(h0);
    float2 f1 = __half22float2(h1);
    v.x += f0.x; v.y += f0.y; v.z += f1.x; v.w += f1.y;
}

__global__ void aggregate_kernel(const float* __restrict__ b1, int n_nodes) {
    int gid = blockIdx.x * (blockDim.x >> 4) + (threadIdx.x >> 4);
    int q   = threadIdx.x & 15;
    if (gid >= n_nodes) return;

    float4 bv = __ldg(reinterpret_cast<const float4*>(&b1[q * 4]));
    float4 v = make_float4(bv.x, bv.y, bv.z, bv.w);
    acc_h4(v, *reinterpret_cast<const uint2*>(&g_yh[(size_t)gid * F_HID + q * 4]));

    int start = gid ? g_cnt[gid - 1] : 0;
    int end   = g_cnt[gid];

    int e = start;
    for (; e + 8 <= end; e += 8) {
        int s[8];
        #pragma unroll
        for (int i = 0; i < 8; i++) s[i] = g_srcs[e + i];
        uint2 a[8];
        #pragma unroll
        for (int i = 0; i < 8; i++)
            a[i] = *reinterpret_cast<const uint2*>(&g_yh[(size_t)s[i] * F_HID + q * 4]);
        #pragma unroll
        for (int i = 0; i < 8; i++) acc_h4(v, a[i]);
    }
    for (; e < end; e++) {
        int s = g_srcs[e];
        acc_h4(v, *reinterpret_cast<const uint2*>(&g_yh[(size_t)s * F_HID + q * 4]));
    }

    __half2 h0 = __floats2half2_rn(fmaxf(v.x, 0.f), fmaxf(v.y, 0.f));
    __half2 h1 = __floats2half2_rn(fmaxf(v.z, 0.f), fmaxf(v.w, 0.f));
    uint2 o = make_uint2(*reinterpret_cast<uint32_t*>(&h0),
                         *reinterpret_cast<uint32_t*>(&h1));
    *reinterpret_cast<uint2*>(&g_ah[(size_t)gid * F_HID + q * 4]) = o;
}

// ---------------------------------------------------------------------------
// Kernel 7: GEMM2: out = A @ W2 + b2, A staged from fp16 g_ah (fp32 compute).
// R5-proven 64x64/4x4 config.
// ---------------------------------------------------------------------------
__global__ void gemm2_kernel(const float* __restrict__ W2,
                             const float* __restrict__ b2,
                             float* __restrict__ out,
                             int n) {
    __shared__ __align__(16) float shA[64 * 68];
    __shared__ __align__(16) float shW[F_HID * F_OUT];
    __shared__ float sb2[F_OUT];

    int tid  = threadIdx.x;
    int row0 = blockIdx.x * 64;

    for (int t = tid; t < F_HID * F_OUT; t += 256) shW[t] = W2[t];
    if (tid < F_OUT) sb2[tid] = b2[tid];

    for (int t = tid; t < 64 * 16; t += 256) {
        int r = t >> 4;
        int q = t & 15;
        int row = row0 + r;
        float4 o = make_float4(0.f, 0.f, 0.f, 0.f);
        if (row < n) {
            uint2 u = *reinterpret_cast<const uint2*>(&g_ah[(size_t)row * F_HID + q * 4]);
            __half2 h0 = *reinterpret_cast<__half2*>(&u.x);
            __half2 h1 = *reinterpret_cast<__half2*>(&u.y);
            float2 f0 = __half22float2(h0);
            float2 f1 = __half22float2(h1);
            o = make_float4(f0.x, f0.y, f1.x, f1.y);
        }
        *reinterpret_cast<float4*>(&shA[r * 68 + q * 4]) = o;
    }
    __syncthreads();

    int ty = tid >> 4;
    int tx = tid & 15;

    float acc[4][4];
    {
        float4 b = *reinterpret_cast<const float4*>(&sb2[tx * 4]);
        #pragma unroll
        for (int i = 0; i < 4; i++) {
            acc[i][0] = b.x; acc[i][1] = b.y; acc[i][2] = b.z; acc[i][3] = b.w;
        }
    }

    const float* ar = &shA[(ty * 4) * 68];
    #pragma unroll 8
    for (int k = 0; k < F_HID; k++) {
        float a0 = ar[0 * 68 + k];
        float a1 = ar[1 * 68 + k];
        float a2 = ar[2 * 68 + k];
        float a3 = ar[3 * 68 + k];
        float4 b = *reinterpret_cast<const float4*>(&shW[k * F_OUT + tx * 4]);
        acc[0][0] = fmaf(a0, b.x, acc[0][0]); acc[0][1] = fmaf(a0, b.y, acc[0][1]);
        acc[0][2] = fmaf(a0, b.z, acc[0][2]); acc[0][3] = fmaf(a0, b.w, acc[0][3]);
        acc[1][0] = fmaf(a1, b.x, acc[1][0]); acc[1][1] = fmaf(a1, b.y, acc[1][1]);
        acc[1][2] = fmaf(a1, b.z, acc[1][2]); acc[1][3] = fmaf(a1, b.w, acc[1][3]);
        acc[2][0] = fmaf(a2, b.x, acc[2][0]); acc[2][1] = fmaf(a2, b.y, acc[2][1]);
        acc[2][2] = fmaf(a2, b.z, acc[2][2]); acc[2][3] = fmaf(a2, b.w, acc[2][3]);
        acc[3][0] = fmaf(a3, b.x, acc[3][0]); acc[3][1] = fmaf(a3, b.y, acc[3][1]);
        acc[3][2] = fmaf(a3, b.z, acc[3][2]); acc[3][3] = fmaf(a3, b.w, acc[3][3]);
    }

    #pragma unroll
    for (int i = 0; i < 4; i++) {
        int row = row0 + ty * 4 + i;
        if (row < n) {
            float4 o = make_float4(acc[i][0], acc[i][1], acc[i][2], acc[i][3]);
            *reinterpret_cast<float4*>(&out[(size_t)row * F_OUT + tx * 4]) = o;
        }
    }
}

// ---------------------------------------------------------------------------
extern "C" void kernel_launch(void* const* d_in, const int* in_sizes, int n_in,
                              void* d_out, int out_size) {
    const float* x  = (const float*)d_in[0];   // [100000, 65]
    const void*  ei = d_in[1];                 // [2, E] int64 or int32 (probed)
    const float* W1 = (const float*)d_in[2];   // [65, 64]
    const float* b1 = (const float*)d_in[3];   // [64]
    const float* W2 = (const float*)d_in[4];   // [64, 64]
    const float* b2 = (const float*)d_in[5];   // [64]
    float*       out = (float*)d_out;          // [100000, 64]

    int n_elems = in_sizes[1];
    int n_edges = n_elems / 2;
    if (n_edges > MAX_EDGES) n_edges = MAX_EDGES;

    // 1) fused: zero counts + sampled dtype probe
    int nprobe = n_elems / 2;
    if (nprobe > 65536) nprobe = 65536;
    init_kernel<<<(N_NODES + 255) / 256, 256>>>((const long long*)ei, nprobe);

    // 2) y = x @ W1  (fp32 compute, fp16 store)
    int nblk = (N_NODES + 63) / 64;
    gemm1_kernel<<<nblk, 256>>>(x, W1, N_NODES);

    // 3) CSR build: histogram -> 2-kernel scan -> fill
    int eblk = (n_edges + 255) / 256;
    hist_kernel<<<eblk, 256>>>(ei, n_edges);
    chunk_sums_kernel<<<NCHUNKS, 256>>>();
    scan_chunks2_kernel<<<NCHUNKS, 256>>>();
    fill_kernel<<<eblk, 256>>>(ei, n_edges);

    // 4) aggregation + layer-1 epilogue -> fp16 g_ah
    int groups_per_block = 256 / 16;
    int ablk = (N_NODES + groups_per_block - 1) / groups_per_block;
    aggregate_kernel<<<ablk, 256>>>(b1, N_NODES);

    // 5) out = A @ W2 + b2
    gemm2_kernel<<<nblk, 256>>>(W2, b2, out, N_NODES);
}

// round 16
// speedup vs baseline: 1.0812x; 1.0812x over previous
#include <cuda_runtime.h>
#include <cuda_fp16.h>
#include <cstdint>

#define N_NODES   100000
#define F_IN      65
#define F_HID     64
#define F_OUT     64
#define MAX_EDGES 1600000
#define NCHUNKS   ((N_NODES + 255) / 256)   // 391

// ---- scratch (~19.7MB; R14-proven) -----------------------------------------
__device__ __align__(16) __half g_yh[(size_t)N_NODES * F_HID]; // y = x@W1 (fp16)
__device__ int g_srcs[MAX_EDGES];    // CSR: src indices grouped by dst
__device__ int g_cnt[N_NODES];       // counts -> excl prefix -> incl end
__device__ int g_bsum[NCHUNKS];      // per-chunk sums for scan
// STICKY flag: 0 = int64 (default), 1 = buffer holds int32 pairs.
__device__ int g_idx_is32;

// ---------------------------------------------------------------------------
// Kernel 1 (fused): zero counts + sampled dtype probe (set-only flag).
// ---------------------------------------------------------------------------
__global__ void init_kernel(const long long* __restrict__ ei, int nprobe) {
    int i = blockIdx.x * blockDim.x + threadIdx.x;
    if (i < N_NODES) g_cnt[i] = 0;
    bool bad = false;
    if (i < nprobe) {
        long long v = ei[i];
        bad = (v < 0) | (v >= N_NODES);
    }
    if (__syncthreads_or(bad) && threadIdx.x == 0) g_idx_is32 = 1;
}

// ---------------------------------------------------------------------------
// Kernel 2 (FUSED): GEMM1 (y = x @ W1, fp16 store) + histogram tail phase.
// GEMM part is the R5-proven 64x64/4x4 config. After the tile store (no
// barrier needed), each thread histograms 4 edges: early blocks' atomic
// phase overlaps late blocks' FMA phase.
// ---------------------------------------------------------------------------
__global__ void gemm1_hist_kernel(const float* __restrict__ x,
                                  const float* __restrict__ W1,
                                  const void* __restrict__ edge_index,
                                  int n_edges, int n) {
    __shared__ float shA[64 * 68];                     // [r][k], stride 68
    __shared__ __align__(16) float shW[F_IN * F_HID];  // [k][j]

    int tid  = threadIdx.x;
    int row0 = blockIdx.x * 64;

    for (int t = tid; t < 64 * F_IN; t += 256) {
        int r = t / F_IN;
        int c = t - r * F_IN;
        int row = row0 + r;
        shA[r * 68 + c] = (row < n) ? x[(size_t)row * F_IN + c] : 0.f;
    }
    for (int t = tid; t < F_IN * F_HID; t += 256) shW[t] = W1[t];
    __syncthreads();

    int ty = tid >> 4;
    int tx = tid & 15;

    float acc[4][4];
    #pragma unroll
    for (int i = 0; i < 4; i++)
        #pragma unroll
        for (int j = 0; j < 4; j++) acc[i][j] = 0.f;

    const float* ar = &shA[(ty * 4) * 68];
    #pragma unroll 5
    for (int k = 0; k < F_IN; k++) {
        float a0 = ar[0 * 68 + k];
        float a1 = ar[1 * 68 + k];
        float a2 = ar[2 * 68 + k];
        float a3 = ar[3 * 68 + k];
        float4 b = *reinterpret_cast<const float4*>(&shW[k * F_HID + tx * 4]);
        acc[0][0] = fmaf(a0, b.x, acc[0][0]); acc[0][1] = fmaf(a0, b.y, acc[0][1]);
        acc[0][2] = fmaf(a0, b.z, acc[0][2]); acc[0][3] = fmaf(a0, b.w, acc[0][3]);
        acc[1][0] = fmaf(a1, b.x, acc[1][0]); acc[1][1] = fmaf(a1, b.y, acc[1][1]);
        acc[1][2] = fmaf(a1, b.z, acc[1][2]); acc[1][3] = fmaf(a1, b.w, acc[1][3]);
        acc[2][0] = fmaf(a2, b.x, acc[2][0]); acc[2][1] = fmaf(a2, b.y, acc[2][1]);
        acc[2][2] = fmaf(a2, b.z, acc[2][2]); acc[2][3] = fmaf(a2, b.w, acc[2][3]);
        acc[3][0] = fmaf(a3, b.x, acc[3][0]); acc[3][1] = fmaf(a3, b.y, acc[3][1]);
        acc[3][2] = fmaf(a3, b.z, acc[3][2]); acc[3][3] = fmaf(a3, b.w, acc[3][3]);
    }

    #pragma unroll
    for (int i = 0; i < 4; i++) {
        int row = row0 + ty * 4 + i;
        if (row < n) {
            __half2 h0 = __floats2half2_rn(acc[i][0], acc[i][1]);
            __half2 h1 = __floats2half2_rn(acc[i][2], acc[i][3]);
            uint2 o = make_uint2(*reinterpret_cast<uint32_t*>(&h0),
                                 *reinterpret_cast<uint32_t*>(&h1));
            *reinterpret_cast<uint2*>(&g_yh[(size_t)row * F_HID + tx * 4]) = o;
        }
    }

    // ---- histogram tail: 4 edges per thread (covers 1.6M with 1563 blocks)
    int gtid = blockIdx.x * 256 + tid;
    int e0 = gtid * 4;
    bool is32 = (g_idx_is32 != 0);
    #pragma unroll
    for (int i = 0; i < 4; i++) {
        int e = e0 + i;
        if (e < n_edges) {
            int dst;
            if (!is32) dst = (int)((const long long*)edge_index)[(size_t)n_edges + e];
            else       dst = ((const int*)edge_index)[n_edges + e];
            atomicAdd(&g_cnt[dst], 1);
        }
    }
}

// ---------------------------------------------------------------------------
// Kernels 3a/3b/3c: 3-level exclusive prefix scan of g_cnt (R14-proven).
// ---------------------------------------------------------------------------
__global__ void chunk_sums_kernel() {
    __shared__ int s[256];
    int b = blockIdx.x, t = threadIdx.x;
    int i = b * 256 + t;
    s[t] = (i < N_NODES) ? g_cnt[i] : 0;
    __syncthreads();
    #pragma unroll
    for (int off = 128; off > 0; off >>= 1) {
        if (t < off) s[t] += s[t + off];
        __syncthreads();
    }
    if (t == 0) g_bsum[b] = s[0];
}

__global__ void scan_bsums_kernel() {
    __shared__ int s[512];
    int t = threadIdx.x;
    int v = (t < NCHUNKS) ? g_bsum[t] : 0;
    s[t] = v;
    __syncthreads();
    #pragma unroll
    for (int off = 1; off < 512; off <<= 1) {
        int add = (t >= off) ? s[t - off] : 0;
        __syncthreads();
        s[t] += add;
        __syncthreads();
    }
    if (t < NCHUNKS) g_bsum[t] = s[t] - v;   // exclusive
}

__global__ void scan_chunks_kernel() {
    __shared__ int s[256];
    int b = blockIdx.x, t = threadIdx.x;
    int i = b * 256 + t;
    int v = (i < N_NODES) ? g_cnt[i] : 0;
    s[t] = v;
    __syncthreads();
    #pragma unroll
    for (int off = 1; off < 256; off <<= 1) {
        int add = (t >= off) ? s[t - off] : 0;
        __syncthreads();
        s[t] += add;
        __syncthreads();
    }
    if (i < N_NODES) g_cnt[i] = g_bsum[b] + s[t] - v;   // exclusive prefix
}

// ---------------------------------------------------------------------------
// Kernel 4: fill CSR (R7-proven 1-edge/thread).
// After this, g_cnt[d] = inclusive end offset of node d.
// ---------------------------------------------------------------------------
__global__ void fill_kernel(const void* __restrict__ edge_index, int n_edges) {
    int e = blockIdx.x * blockDim.x + threadIdx.x;
    if (e >= n_edges) return;
    int src, dst;
    if (!g_idx_is32) {
        const long long* p = (const long long*)edge_index;
        src = (int)p[e];
        dst = (int)p[(size_t)n_edges + e];
    } else {
        const int* p = (const int*)edge_index;
        src = p[e];
        dst = p[n_edges + e];
    }
    int pos = atomicAdd(&g_cnt[dst], 1);
    g_srcs[pos] = src;
}

// ---------------------------------------------------------------------------
// Kernel 5: aggregation + layer-1 epilogue (fp16 gathers, fp32 accumulate):
//   out[node] = relu( y[node] + b1 + sum_{src in-edges} y[src] )
// 16-lane group per node; lane q owns halves [q*4, q*4+4); 8-way unroll.
// ---------------------------------------------------------------------------
__device__ __forceinline__ void acc_h4(float4& v, uint2 u) {
    __half2 h0 = *reinterpret_cast<__half2*>(&u.x);
    __half2 h1 = *reinterpret_cast<__half2*>(&u.y);
    float2 f0 = __half22float2(h0);
    float2 f1 = __half22float2(h1);
    v.x += f0.x; v.y += f0.y; v.z += f1.x; v.w += f1.y;
}

__global__ void aggregate_kernel(const float* __restrict__ b1,
                                 float* __restrict__ out, int n_nodes) {
    int gid = blockIdx.x * (blockDim.x >> 4) + (threadIdx.x >> 4);
    int q   = threadIdx.x & 15;
    if (gid >= n_nodes) return;

    float4 bv = __ldg(reinterpret_cast<const float4*>(&b1[q * 4]));
    float4 v = make_float4(bv.x, bv.y, bv.z, bv.w);
    acc_h4(v, *reinterpret_cast<const uint2*>(&g_yh[(size_t)gid * F_HID + q * 4]));

    int start = gid ? g_cnt[gid - 1] : 0;
    int end   = g_cnt[gid];

    int e = start;
    for (; e + 8 <= end; e += 8) {
        int s[8];
        #pragma unroll
        for (int i = 0; i < 8; i++) s[i] = g_srcs[e + i];
        uint2 a[8];
        #pragma unroll
        for (int i = 0; i < 8; i++)
            a[i] = *reinterpret_cast<const uint2*>(&g_yh[(size_t)s[i] * F_HID + q * 4]);
        #pragma unroll
        for (int i = 0; i < 8; i++) acc_h4(v, a[i]);
    }
    for (; e < end; e++) {
        int s = g_srcs[e];
        acc_h4(v, *reinterpret_cast<const uint2*>(&g_yh[(size_t)s * F_HID + q * 4]));
    }

    v.x = fmaxf(v.x, 0.f); v.y = fmaxf(v.y, 0.f);
    v.z = fmaxf(v.z, 0.f); v.w = fmaxf(v.w, 0.f);
    *reinterpret_cast<float4*>(&out[(size_t)gid * F_HID + q * 4]) = v;
}

// ---------------------------------------------------------------------------
// Kernel 6: GEMM2 (in-place on d_out): out = A @ W2 + b2, A = d_out rows.
// R5-proven scalar 64x64/4x4 config (R14-proven fp32 path).
// ---------------------------------------------------------------------------
__global__ void gemm2_kernel(const float* __restrict__ W2,
                             const float* __restrict__ b2,
                             float* __restrict__ out,
                             int n) {
    __shared__ __align__(16) float shA[64 * 68];
    __shared__ __align__(16) float shW[F_HID * F_OUT];
    __shared__ float sb2[F_OUT];

    int tid  = threadIdx.x;
    int row0 = blockIdx.x * 64;

    for (int t = tid; t < F_HID * F_OUT; t += 256) shW[t] = W2[t];
    if (tid < F_OUT) sb2[tid] = b2[tid];

    for (int t = tid; t < 64 * 16; t += 256) {
        int r = t >> 4;
        int q = t & 15;
        int row = row0 + r;
        float4 o = make_float4(0.f, 0.f, 0.f, 0.f);
        if (row < n)
            o = *reinterpret_cast<const float4*>(&out[(size_t)row * F_HID + q * 4]);
        *reinterpret_cast<float4*>(&shA[r * 68 + q * 4]) = o;
    }
    __syncthreads();

    int ty = tid >> 4;
    int tx = tid & 15;

    float acc[4][4];
    {
        float4 b = *reinterpret_cast<const float4*>(&sb2[tx * 4]);
        #pragma unroll
        for (int i = 0; i < 4; i++) {
            acc[i][0] = b.x; acc[i][1] = b.y; acc[i][2] = b.z; acc[i][3] = b.w;
        }
    }

    const float* ar = &shA[(ty * 4) * 68];
    #pragma unroll 8
    for (int k = 0; k < F_HID; k++) {
        float a0 = ar[0 * 68 + k];
        float a1 = ar[1 * 68 + k];
        float a2 = ar[2 * 68 + k];
        float a3 = ar[3 * 68 + k];
        float4 b = *reinterpret_cast<const float4*>(&shW[k * F_OUT + tx * 4]);
        acc[0][0] = fmaf(a0, b.x, acc[0][0]); acc[0][1] = fmaf(a0, b.y, acc[0][1]);
        acc[0][2] = fmaf(a0, b.z, acc[0][2]); acc[0][3] = fmaf(a0, b.w, acc[0][3]);
        acc[1][0] = fmaf(a1, b.x, acc[1][0]); acc[1][1] = fmaf(a1, b.y, acc[1][1]);
        acc[1][2] = fmaf(a1, b.z, acc[1][2]); acc[1][3] = fmaf(a1, b.w, acc[1][3]);
        acc[2][0] = fmaf(a2, b.x, acc[2][0]); acc[2][1] = fmaf(a2, b.y, acc[2][1]);
        acc[2][2] = fmaf(a2, b.z, acc[2][2]); acc[2][3] = fmaf(a2, b.w, acc[2][3]);
        acc[3][0] = fmaf(a3, b.x, acc[3][0]); acc[3][1] = fmaf(a3, b.y, acc[3][1]);
        acc[3][2] = fmaf(a3, b.z, acc[3][2]); acc[3][3] = fmaf(a3, b.w, acc[3][3]);
    }

    #pragma unroll
    for (int i = 0; i < 4; i++) {
        int row = row0 + ty * 4 + i;
        if (row < n) {
            float4 o = make_float4(acc[i][0], acc[i][1], acc[i][2], acc[i][3]);
            *reinterpret_cast<float4*>(&out[(size_t)row * F_OUT + tx * 4]) = o;
        }
    }
}

// ---------------------------------------------------------------------------
extern "C" void kernel_launch(void* const* d_in, const int* in_sizes, int n_in,
                              void* d_out, int out_size) {
    const float* x  = (const float*)d_in[0];   // [100000, 65]
    const void*  ei = d_in[1];                 // [2, E] int64 or int32 (probed)
    const float* W1 = (const float*)d_in[2];   // [65, 64]
    const float* b1 = (const float*)d_in[3];   // [64]
    const float* W2 = (const float*)d_in[4];   // [64, 64]
    const float* b2 = (const float*)d_in[5];   // [64]
    float*       out = (float*)d_out;          // [100000, 64]

    int n_elems = in_sizes[1];
    int n_edges = n_elems / 2;
    if (n_edges > MAX_EDGES) n_edges = MAX_EDGES;

    // 1) fused: zero counts + sampled dtype probe
    int nprobe = n_elems / 2;
    if (nprobe > 65536) nprobe = 65536;
    init_kernel<<<(N_NODES + 255) / 256, 256>>>((const long long*)ei, nprobe);

    // 2) y = x @ W1 (fp16 store) + histogram tail phase
    int nblk = (N_NODES + 63) / 64;   // 1563; x 256 thr x 4 edges >= 1.6M
    gemm1_hist_kernel<<<nblk, 256>>>(x, W1, ei, n_edges, N_NODES);

    // 3) exclusive scan of counts (R14-proven 3-kernel path)
    chunk_sums_kernel<<<NCHUNKS, 256>>>();
    scan_bsums_kernel<<<1, 512>>>();
    scan_chunks_kernel<<<NCHUNKS, 256>>>();

    // 4) fill CSR
    int eblk = (n_edges + 255) / 256;
    fill_kernel<<<eblk, 256>>>(ei, n_edges);

    // 5) aggregation + layer-1 epilogue (fp16 gathers, fp32 accumulate)
    int groups_per_block = 256 / 16;
    int ablk = (N_NODES + groups_per_block - 1) / groups_per_block;
    aggregate_kernel<<<ablk, 256>>>(b1, out, N_NODES);

    // 6) out = out @ W2 + b2   (in-place, scalar fp32)
    gemm2_kernel<<<nblk, 256>>>(W2, b2, out, N_NODES);
}

// round 17
// speedup vs baseline: 1.0923x; 1.0103x over previous
#include <cuda_runtime.h>
#include <cuda_fp16.h>
#include <cstdint>

#define N_NODES   100000
#define F_IN      65
#define F_HID     64
#define F_OUT     64
#define MAX_EDGES 1600000
#define NCHUNKS   ((N_NODES + 255) / 256)   // 391

// ---- scratch (~19.7MB; R14/R16-proven) -------------------------------------
__device__ __align__(16) __half g_yh[(size_t)N_NODES * F_HID]; // y = x@W1 (fp16)
__device__ int g_srcs[MAX_EDGES];    // CSR: src indices grouped by dst
__device__ int g_cnt[N_NODES];       // counts -> excl prefix -> incl end
__device__ int g_bsum[NCHUNKS];      // per-chunk sums for scan
// STICKY flag: 0 = int64 (default), 1 = buffer holds int32 pairs.
__device__ int g_idx_is32;

// ---------------------------------------------------------------------------
// Kernel 1 (fused): zero counts + sampled dtype probe (set-only flag).
// ---------------------------------------------------------------------------
__global__ void init_kernel(const long long* __restrict__ ei, int nprobe) {
    int i = blockIdx.x * blockDim.x + threadIdx.x;
    if (i < N_NODES) g_cnt[i] = 0;
    bool bad = false;
    if (i < nprobe) {
        long long v = ei[i];
        bad = (v < 0) | (v >= N_NODES);
    }
    if (__syncthreads_or(bad) && threadIdx.x == 0) g_idx_is32 = 1;
}

// ---------------------------------------------------------------------------
// Kernel 2 (FUSED, R16-proven): GEMM1 (y = x @ W1, fp16 store) + hist tail.
// ---------------------------------------------------------------------------
__global__ void gemm1_hist_kernel(const float* __restrict__ x,
                                  const float* __restrict__ W1,
                                  const void* __restrict__ edge_index,
                                  int n_edges, int n) {
    __shared__ float shA[64 * 68];                     // [r][k], stride 68
    __shared__ __align__(16) float shW[F_IN * F_HID];  // [k][j]

    int tid  = threadIdx.x;
    int row0 = blockIdx.x * 64;

    for (int t = tid; t < 64 * F_IN; t += 256) {
        int r = t / F_IN;
        int c = t - r * F_IN;
        int row = row0 + r;
        shA[r * 68 + c] = (row < n) ? x[(size_t)row * F_IN + c] : 0.f;
    }
    for (int t = tid; t < F_IN * F_HID; t += 256) shW[t] = W1[t];
    __syncthreads();

    int ty = tid >> 4;
    int tx = tid & 15;

    float acc[4][4];
    #pragma unroll
    for (int i = 0; i < 4; i++)
        #pragma unroll
        for (int j = 0; j < 4; j++) acc[i][j] = 0.f;

    const float* ar = &shA[(ty * 4) * 68];
    #pragma unroll 5
    for (int k = 0; k < F_IN; k++) {
        float a0 = ar[0 * 68 + k];
        float a1 = ar[1 * 68 + k];
        float a2 = ar[2 * 68 + k];
        float a3 = ar[3 * 68 + k];
        float4 b = *reinterpret_cast<const float4*>(&shW[k * F_HID + tx * 4]);
        acc[0][0] = fmaf(a0, b.x, acc[0][0]); acc[0][1] = fmaf(a0, b.y, acc[0][1]);
        acc[0][2] = fmaf(a0, b.z, acc[0][2]); acc[0][3] = fmaf(a0, b.w, acc[0][3]);
        acc[1][0] = fmaf(a1, b.x, acc[1][0]); acc[1][1] = fmaf(a1, b.y, acc[1][1]);
        acc[1][2] = fmaf(a1, b.z, acc[1][2]); acc[1][3] = fmaf(a1, b.w, acc[1][3]);
        acc[2][0] = fmaf(a2, b.x, acc[2][0]); acc[2][1] = fmaf(a2, b.y, acc[2][1]);
        acc[2][2] = fmaf(a2, b.z, acc[2][2]); acc[2][3] = fmaf(a2, b.w, acc[2][3]);
        acc[3][0] = fmaf(a3, b.x, acc[3][0]); acc[3][1] = fmaf(a3, b.y, acc[3][1]);
        acc[3][2] = fmaf(a3, b.z, acc[3][2]); acc[3][3] = fmaf(a3, b.w, acc[3][3]);
    }

    #pragma unroll
    for (int i = 0; i < 4; i++) {
        int row = row0 + ty * 4 + i;
        if (row < n) {
            __half2 h0 = __floats2half2_rn(acc[i][0], acc[i][1]);
            __half2 h1 = __floats2half2_rn(acc[i][2], acc[i][3]);
            uint2 o = make_uint2(*reinterpret_cast<uint32_t*>(&h0),
                                 *reinterpret_cast<uint32_t*>(&h1));
            *reinterpret_cast<uint2*>(&g_yh[(size_t)row * F_HID + tx * 4]) = o;
        }
    }

    // ---- histogram tail: 4 edges per thread
    int gtid = blockIdx.x * 256 + tid;
    int e0 = gtid * 4;
    bool is32 = (g_idx_is32 != 0);
    #pragma unroll
    for (int i = 0; i < 4; i++) {
        int e = e0 + i;
        if (e < n_edges) {
            int dst;
            if (!is32) dst = (int)((const long long*)edge_index)[(size_t)n_edges + e];
            else       dst = ((const int*)edge_index)[n_edges + e];
            atomicAdd(&g_cnt[dst], 1);
        }
    }
}

// ---------------------------------------------------------------------------
// Kernel 3a: per-chunk sums.
// ---------------------------------------------------------------------------
__global__ void chunk_sums_kernel() {
    __shared__ int s[256];
    int b = blockIdx.x, t = threadIdx.x;
    int i = b * 256 + t;
    s[t] = (i < N_NODES) ? g_cnt[i] : 0;
    __syncthreads();
    #pragma unroll
    for (int off = 128; off > 0; off >>= 1) {
        if (t < off) s[t] += s[t + off];
        __syncthreads();
    }
    if (t == 0) g_bsum[b] = s[0];
}

// ---------------------------------------------------------------------------
// Kernel 3b (SINGLE-DELTA TEST): combined scan. Block b reduces g_bsum[0..b)
// itself (<=391 ints over 256 threads), then exclusive-scans its own chunk.
// Replaces scan_bsums + scan_chunks (one fewer launch).
// ---------------------------------------------------------------------------
__global__ void scan_chunks2_kernel() {
    __shared__ int s[256];
    __shared__ int sbase;
    int b = blockIdx.x, t = threadIdx.x;

    int part = 0;
    for (int i = t; i < b; i += 256) part += g_bsum[i];
    s[t] = part;
    __syncthreads();
    #pragma unroll
    for (int off = 128; off > 0; off >>= 1) {
        if (t < off) s[t] += s[t + off];
        __syncthreads();
    }
    if (t == 0) sbase = s[0];
    __syncthreads();
    int base = sbase;
    __syncthreads();

    int i = b * 256 + t;
    int v = (i < N_NODES) ? g_cnt[i] : 0;
    s[t] = v;
    __syncthreads();
    #pragma unroll
    for (int off = 1; off < 256; off <<= 1) {
        int add = (t >= off) ? s[t - off] : 0;
        __syncthreads();
        s[t] += add;
        __syncthreads();
    }
    if (i < N_NODES) g_cnt[i] = base + s[t] - v;   // exclusive prefix
}

// ---------------------------------------------------------------------------
// Kernel 4: fill CSR (R7-proven 1-edge/thread).
// After this, g_cnt[d] = inclusive end offset of node d.
// ---------------------------------------------------------------------------
__global__ void fill_kernel(const void* __restrict__ edge_index, int n_edges) {
    int e = blockIdx.x * blockDim.x + threadIdx.x;
    if (e >= n_edges) return;
    int src, dst;
    if (!g_idx_is32) {
        const long long* p = (const long long*)edge_index;
        src = (int)p[e];
        dst = (int)p[(size_t)n_edges + e];
    } else {
        const int* p = (const int*)edge_index;
        src = p[e];
        dst = p[n_edges + e];
    }
    int pos = atomicAdd(&g_cnt[dst], 1);
    g_srcs[pos] = src;
}

// ---------------------------------------------------------------------------
// Kernel 5: aggregation + layer-1 epilogue (fp16 gathers, fp32 accumulate):
//   out[node] = relu( y[node] + b1 + sum_{src in-edges} y[src] )
// ---------------------------------------------------------------------------
__device__ __forceinline__ void acc_h4(float4& v, uint2 u) {
    __half2 h0 = *reinterpret_cast<__half2*>(&u.x);
    __half2 h1 = *reinterpret_cast<__half2*>(&u.y);
    float2 f0 = __half22float2(h0);
    float2 f1 = __half22float2(h1);
    v.x += f0.x; v.y += f0.y; v.z += f1.x; v.w += f1.y;
}

__global__ void aggregate_kernel(const float* __restrict__ b1,
                                 float* __restrict__ out, int n_nodes) {
    int gid = blockIdx.x * (blockDim.x >> 4) + (threadIdx.x >> 4);
    int q   = threadIdx.x & 15;
    if (gid >= n_nodes) return;

    float4 bv = __ldg(reinterpret_cast<const float4*>(&b1[q * 4]));
    float4 v = make_float4(bv.x, bv.y, bv.z, bv.w);
    acc_h4(v, *reinterpret_cast<const uint2*>(&g_yh[(size_t)gid * F_HID + q * 4]));

    int start = gid ? g_cnt[gid - 1] : 0;
    int end   = g_cnt[gid];

    int e = start;
    for (; e + 8 <= end; e += 8) {
        int s[8];
        #pragma unroll
        for (int i = 0; i < 8; i++) s[i] = g_srcs[e + i];
        uint2 a[8];
        #pragma unroll
        for (int i = 0; i < 8; i++)
            a[i] = *reinterpret_cast<const uint2*>(&g_yh[(size_t)s[i] * F_HID + q * 4]);
        #pragma unroll
        for (int i = 0; i < 8; i++) acc_h4(v, a[i]);
    }
    for (; e < end; e++) {
        int s = g_srcs[e];
        acc_h4(v, *reinterpret_cast<const uint2*>(&g_yh[(size_t)s * F_HID + q * 4]));
    }

    v.x = fmaxf(v.x, 0.f); v.y = fmaxf(v.y, 0.f);
    v.z = fmaxf(v.z, 0.f); v.w = fmaxf(v.w, 0.f);
    *reinterpret_cast<float4*>(&out[(size_t)gid * F_HID + q * 4]) = v;
}

// ---------------------------------------------------------------------------
// Kernel 6: GEMM2 (in-place on d_out): out = A @ W2 + b2, A = d_out rows.
// ---------------------------------------------------------------------------
__global__ void gemm2_kernel(const float* __restrict__ W2,
                             const float* __restrict__ b2,
                             float* __restrict__ out,
                             int n) {
    __shared__ __align__(16) float shA[64 * 68];
    __shared__ __align__(16) float shW[F_HID * F_OUT];
    __shared__ float sb2[F_OUT];

    int tid  = threadIdx.x;
    int row0 = blockIdx.x * 64;

    for (int t = tid; t < F_HID * F_OUT; t += 256) shW[t] = W2[t];
    if (tid < F_OUT) sb2[tid] = b2[tid];

    for (int t = tid; t < 64 * 16; t += 256) {
        int r = t >> 4;
        int q = t & 15;
        int row = row0 + r;
        float4 o = make_float4(0.f, 0.f, 0.f, 0.f);
        if (row < n)
            o = *reinterpret_cast<const float4*>(&out[(size_t)row * F_HID + q * 4]);
        *reinterpret_cast<float4*>(&shA[r * 68 + q * 4]) = o;
    }
    __syncthreads();

    int ty = tid >> 4;
    int tx = tid & 15;

    float acc[4][4];
    {
        float4 b = *reinterpret_cast<const float4*>(&sb2[tx * 4]);
        #pragma unroll
        for (int i = 0; i < 4; i++) {
            acc[i][0] = b.x; acc[i][1] = b.y; acc[i][2] = b.z; acc[i][3] = b.w;
        }
    }

    const float* ar = &shA[(ty * 4) * 68];
    #pragma unroll 8
    for (int k = 0; k < F_HID; k++) {
        float a0 = ar[0 * 68 + k];
        float a1 = ar[1 * 68 + k];
        float a2 = ar[2 * 68 + k];
        float a3 = ar[3 * 68 + k];
        float4 b = *reinterpret_cast<const float4*>(&shW[k * F_OUT + tx * 4]);
        acc[0][0] = fmaf(a0, b.x, acc[0][0]); acc[0][1] = fmaf(a0, b.y, acc[0][1]);
        acc[0][2] = fmaf(a0, b.z, acc[0][2]); acc[0][3] = fmaf(a0, b.w, acc[0][3]);
        acc[1][0] = fmaf(a1, b.x, acc[1][0]); acc[1][1] = fmaf(a1, b.y, acc[1][1]);
        acc[1][2] = fmaf(a1, b.z, acc[1][2]); acc[1][3] = fmaf(a1, b.w, acc[1][3]);
        acc[2][0] = fmaf(a2, b.x, acc[2][0]); acc[2][1] = fmaf(a2, b.y, acc[2][1]);
        acc[2][2] = fmaf(a2, b.z, acc[2][2]); acc[2][3] = fmaf(a2, b.w, acc[2][3]);
        acc[3][0] = fmaf(a3, b.x, acc[3][0]); acc[3][1] = fmaf(a3, b.y, acc[3][1]);
        acc[3][2] = fmaf(a3, b.z, acc[3][2]); acc[3][3] = fmaf(a3, b.w, acc[3][3]);
    }

    #pragma unroll
    for (int i = 0; i < 4; i++) {
        int row = row0 + ty * 4 + i;
        if (row < n) {
            float4 o = make_float4(acc[i][0], acc[i][1], acc[i][2], acc[i][3]);
            *reinterpret_cast<float4*>(&out[(size_t)row * F_OUT + tx * 4]) = o;
        }
    }
}

// ---------------------------------------------------------------------------
extern "C" void kernel_launch(void* const* d_in, const int* in_sizes, int n_in,
                              void* d_out, int out_size) {
    const float* x  = (const float*)d_in[0];   // [100000, 65]
    const void*  ei = d_in[1];                 // [2, E] int64 or int32 (probed)
    const float* W1 = (const float*)d_in[2];   // [65, 64]
    const float* b1 = (const float*)d_in[3];   // [64]
    const float* W2 = (const float*)d_in[4];   // [64, 64]
    const float* b2 = (const float*)d_in[5];   // [64]
    float*       out = (float*)d_out;          // [100000, 64]

    int n_elems = in_sizes[1];
    int n_edges = n_elems / 2;
    if (n_edges > MAX_EDGES) n_edges = MAX_EDGES;

    // 1) fused: zero counts + sampled dtype probe
    int nprobe = n_elems / 2;
    if (nprobe > 65536) nprobe = 65536;
    init_kernel<<<(N_NODES + 255) / 256, 256>>>((const long long*)ei, nprobe);

    // 2) y = x @ W1 (fp16 store) + histogram tail phase
    int nblk = (N_NODES + 63) / 64;   // 1563; x 256 thr x 4 edges >= 1.6M
    gemm1_hist_kernel<<<nblk, 256>>>(x, W1, ei, n_edges, N_NODES);

    // 3) exclusive scan of counts (2-kernel path — single delta under test)
    chunk_sums_kernel<<<NCHUNKS, 256>>>();
    scan_chunks2_kernel<<<NCHUNKS, 256>>>();

    // 4) fill CSR
    int eblk = (n_edges + 255) / 256;
    fill_kernel<<<eblk, 256>>>(ei, n_edges);

    // 5) aggregation + layer-1 epilogue (fp16 gathers, fp32 accumulate)
    int groups_per_block = 256 / 16;
    int ablk = (N_NODES + groups_per_block - 1) / groups_per_block;
    aggregate_kernel<<<ablk, 256>>>(b1, out, N_NODES);

    // 6) out = out @ W2 + b2   (in-place, scalar fp32)
    gemm2_kernel<<<nblk, 256>>>(W2, b2, out, N_NODES);
}